// round 16
// baseline (speedup 1.0000x reference)
#include <cuda_runtime.h>
#include <cuda_fp16.h>
#include <stdint.h>

#define NATOMS 10000
#define NPAD   10112   // NATOMS rounded up to 32; tail rows zeroed
#define F      128
#define NEDGES 640000
#define CAP    256     // per-node bucket capacity (deg ~ Poisson(64); P(>256) ~ 1e-80)
#define NTILES (NPAD / 32)   // 316
#define GGRID  148           // persistent GEMM: one block per SM

typedef unsigned long long u64_t;

// Scratch (static; no allocations allowed).
// g_deg is zero at module load and re-zeroed inside out_gemm each call,
// so prebuild_kernel can start its atomic histogram immediately.
__device__ __align__(16) __half g_X16[NPAD * 384];   // [feat | S | deg*feat] fp16
__device__ __align__(16) __half g_W16[384 * F];      // folded weights fp16 [k][n]
__device__ __align__(16) int    g_deg[NATOMS];       // in-degree (also fill cursor)
__device__ int   g_csr[NATOMS * CAP];                // src indices bucketed by dst
__device__ float g_c[F];                             // b_msg @ Wu_bot (fp32)

// ---------------------------------------------------------------------------
// Fused pre+build (unchanged from R15 — at its wavefront floor).
// ---------------------------------------------------------------------------
__global__ void __launch_bounds__(256) prebuild_kernel(const float* __restrict__ feat,
                                                       const void*  __restrict__ ei,
                                                       const float* __restrict__ W_msg,
                                                       const float* __restrict__ b_msg,
                                                       const float* __restrict__ W_upd) {
    int b = blockIdx.x, t = threadIdx.x;
    int gi = b * 256 + t;

    bool is64 = true;
    {
        const long long* p = (const long long*)ei;
#pragma unroll
        for (int k = 0; k < 8; ++k) {
            long long v = p[k];
            if (v < 0 || v >= NATOMS) is64 = false;
        }
    }

    int s0, s1, d0, d1;
    if (is64) {
        const long long* ps = (const long long*)ei;
        const long long* pd = ps + NEDGES;
        int base = gi * 2;
        s0 = (int)ps[base]; s1 = (int)ps[base + 1];
        d0 = (int)pd[base]; d1 = (int)pd[base + 1];
    } else {
        int2 sv = ((const int2*)((const int*)ei))[gi];
        int2 dv = ((const int2*)((const int*)ei + NEDGES))[gi];
        s0 = sv.x; s1 = sv.y;
        d0 = dv.x; d1 = dv.y;
    }
    int p0 = atomicAdd(&g_deg[d0], 1);
    int p1 = atomicAdd(&g_deg[d1], 1);

    {   // fp32 -> fp16 convert (hides atomic return latency)
        int row = gi >> 5, seg = gi & 31;
        float4 v = __ldg((const float4*)feat + gi);
        __half2 h0 = __float22half2_rn(make_float2(v.x, v.y));
        __half2 h1 = __float22half2_rn(make_float2(v.z, v.w));
        uint2 p;
        p.x = *(unsigned*)&h0;
        p.y = *(unsigned*)&h1;
        ((uint2*)g_X16)[row * 96 + seg] = p;
    }
    if (gi < 10752) ((uint2*)g_X16)[NATOMS * 96 + gi] = make_uint2(0u, 0u);

    g_csr[d0 * CAP + p0] = s0;
    g_csr[d1 * CAP + p1] = s1;

    if (b >= 625 && b < 754) {
        int i = b - 625;
        int j = t & 127, half = t >> 7;
        if (i < 128) {
            float acc = 0.f;
            if (half == 0) {
#pragma unroll 8
                for (int k = 0; k < 128; ++k)
                    acc += W_msg[i * F + k] * W_upd[(128 + k) * F + j];
                g_W16[(128 + i) * F + j] = __float2half(acc);
            } else {
#pragma unroll 8
                for (int k = 0; k < 128; ++k)
                    acc += W_msg[(128 + i) * F + k] * W_upd[(128 + k) * F + j];
                g_W16[(256 + i) * F + j] = __float2half(acc);
            }
        } else {
            for (int r = half * 64; r < half * 64 + 64; ++r)
                g_W16[r * F + j] = __float2half(W_upd[r * F + j]);
            if (half == 0) {
                float c = 0.f;
#pragma unroll 8
                for (int k = 0; k < 128; ++k)
                    c += b_msg[k] * W_upd[(128 + k) * F + j];
                g_c[j] = c;
            }
        }
    }
}

// ---------------------------------------------------------------------------
// Gather (unchanged — L2-BW floor).
// ---------------------------------------------------------------------------
__device__ __forceinline__ void acc_h4(float4& acc, uint2 p) {
    __half2 h0 = *(__half2*)&p.x;
    __half2 h1 = *(__half2*)&p.y;
    float2 f0 = __half22float2(h0);
    float2 f1 = __half22float2(h1);
    acc.x += f0.x; acc.y += f0.y; acc.z += f1.x; acc.w += f1.y;
}
__device__ __forceinline__ uint2 pack_h4(float4 v) {
    __half2 h0 = __float22half2_rn(make_float2(v.x, v.y));
    __half2 h1 = __float22half2_rn(make_float2(v.z, v.w));
    uint2 p;
    p.x = *(unsigned*)&h0;
    p.y = *(unsigned*)&h1;
    return p;
}

__global__ void __launch_bounds__(256) gather_kernel() {
    int warp = (blockIdx.x * blockDim.x + threadIdx.x) >> 5;
    int lane = threadIdx.x & 31;
    if (warp >= NATOMS) return;

    const int* bucket = g_csr + warp * CAP;
    const uint2* f16 = (const uint2*)g_X16;
    int n = g_deg[warp];
    int j = 0;
    float4 acc = make_float4(0.f, 0.f, 0.f, 0.f);

    while (n - j >= 32) {
        int s = bucket[j + lane];
#pragma unroll
        for (int i = 0; i < 32; i += 8) {
            uint2 v[8];
#pragma unroll
            for (int q = 0; q < 8; ++q) {
                int sq = __shfl_sync(0xffffffffu, s, i + q);
                v[q] = __ldg(f16 + sq * 96 + lane);
            }
#pragma unroll
            for (int q = 0; q < 8; ++q) acc_h4(acc, v[q]);
        }
        j += 32;
    }
    if (j < n) {
        int rem = n - j;
        int s = (lane < rem) ? bucket[j + lane] : 0;
        for (int i = 0; i < rem; ++i) {
            int si = __shfl_sync(0xffffffffu, s, i);
            uint2 v = __ldg(f16 + si * 96 + lane);
            acc_h4(acc, v);
        }
    }
    ((uint2*)g_X16)[warp * 96 + 32 + lane] = pack_h4(acc);
    float d = (float)n;
    uint2 fv = __ldg(f16 + warp * 96 + lane);
    __half2 h0 = *(__half2*)&fv.x;
    __half2 h1 = *(__half2*)&fv.y;
    float2 f0 = __half22float2(h0);
    float2 f1 = __half22float2(h1);
    ((uint2*)g_X16)[warp * 96 + 64 + lane] =
        pack_h4(make_float4(f0.x * d, f0.y * d, f1.x * d, f1.y * d));
}

// ---------------------------------------------------------------------------
// Persistent-W tensor-core GEMM: grid = 148 (one wave), each block loads the
// FULL W16 (384 x pitch136 = 102 KB) into smem ONCE, then grid-strides over
// 32-row tiles (316 tiles, <=3/block). W L2 traffic 30 MB -> 14 MB.
// X double-buffered with register prefetch. Fragment maps identical to R15.
// Smem: W 384*136*2 = 104448 B + X 2*32*72*2 = 9216 B = 113664 B.
// ---------------------------------------------------------------------------
__device__ __forceinline__ void ldsm_x4(uint32_t r[4], uint32_t addr) {
    asm volatile("ldmatrix.sync.aligned.m8n8.x4.shared.b16 {%0,%1,%2,%3}, [%4];"
                 : "=r"(r[0]), "=r"(r[1]), "=r"(r[2]), "=r"(r[3]) : "r"(addr));
}
__device__ __forceinline__ void ldsm_x4_t(uint32_t r[4], uint32_t addr) {
    asm volatile("ldmatrix.sync.aligned.m8n8.x4.trans.shared.b16 {%0,%1,%2,%3}, [%4];"
                 : "=r"(r[0]), "=r"(r[1]), "=r"(r[2]), "=r"(r[3]) : "r"(addr));
}
__device__ __forceinline__ void mma16816(float d[4], const uint32_t a[4],
                                         uint32_t b0, uint32_t b1) {
    asm volatile("mma.sync.aligned.m16n8k16.row.col.f32.f16.f16.f32 "
                 "{%0,%1,%2,%3}, {%4,%5,%6,%7}, {%8,%9}, {%0,%1,%2,%3};"
                 : "+f"(d[0]), "+f"(d[1]), "+f"(d[2]), "+f"(d[3])
                 : "r"(a[0]), "r"(a[1]), "r"(a[2]), "r"(a[3]), "r"(b0), "r"(b1));
}

#define XPITCH 72
#define WPITCH 136
#define GEMM_SMEM_BYTES (384 * WPITCH * 2 + 2 * 32 * XPITCH * 2)

__global__ void __launch_bounds__(256) out_gemm(const float* __restrict__ b_upd,
                                                float* __restrict__ out) {
    extern __shared__ __align__(16) __half smem[];
    __half* Ws = smem;                               // 384 x 136 (full W)
    __half* XsBuf[2] = { smem + 384 * WPITCH, smem + 384 * WPITCH + 32 * XPITCH };

    int tid  = threadIdx.x;
    int lane = tid & 31, wid = tid >> 5;
    int wm = wid >> 2;               // 0..1 -> rows wm*16
    int wn = wid & 3;                // 0..3 -> cols wn*32

    // ---- load FULL W into smem once: 384 rows x 16 uint4 = 6144; 24/thread ----
#pragma unroll
    for (int i = 0; i < 24; ++i) {
        int idx = tid + i * 256;
        int row = idx >> 4, seg = idx & 15;
        uint4 v = __ldg((const uint4*)g_W16 + row * 16 + seg);
        *(uint4*)&Ws[row * WPITCH + seg * 8] = v;
    }

    // ---- hoisted epilogue constants ----
    int colbase = wn * 32 + (lane & 3) * 2;
    float2 cv[4], bv[4];
#pragma unroll
    for (int nt = 0; nt < 4; ++nt) {
        int col = colbase + nt * 8;
        cv[nt] = make_float2(g_c[col], g_c[col + 1]);
        bv[nt] = make_float2(__ldg(&b_upd[col]), __ldg(&b_upd[col + 1]));
    }
    __syncthreads();                                 // W + constants ready

    uint4 xv;
    auto loadX = [&](int bm, int c) {
        int row = tid >> 3, seg = tid & 7;
        xv = __ldg((const uint4*)g_X16 + (u64_t)(bm + row) * 48 + c * 8 + seg);
    };
    auto storeX = [&](int buf) {
        int row = tid >> 3, seg = tid & 7;
        *(uint4*)&XsBuf[buf][row * XPITCH + seg * 8] = xv;
    };

#pragma unroll 1
    for (int tile = blockIdx.x; tile < NTILES; tile += GGRID) {
        int bm = tile * 32;

        float acc[4][4];
#pragma unroll
        for (int nt = 0; nt < 4; ++nt)
#pragma unroll
            for (int q = 0; q < 4; ++q) acc[nt][q] = 0.f;

        loadX(bm, 0);
        storeX(0);                                   // safe: post-epilogue barrier
        __syncthreads();
#pragma unroll 1
        for (int c = 0; c < 6; ++c) {
            if (c < 5) loadX(bm, c + 1);
            const __half* Xp = XsBuf[c & 1];
            const __half* Wc = Ws + c * 64 * WPITCH;
#pragma unroll
            for (int ks = 0; ks < 4; ++ks) {
                uint32_t a[4];
                int arow = wm * 16 + (lane & 15);
                int acol = ks * 16 + ((lane >> 4) << 3);
                ldsm_x4(a, (uint32_t)__cvta_generic_to_shared(&Xp[arow * XPITCH + acol]));
                uint32_t bfr[2][4];
                int krow = ks * 16 + (lane & 7) + (((lane >> 3) & 1) << 3);
                int noff = ((lane >> 4) << 3);
#pragma unroll
                for (int nt4 = 0; nt4 < 2; ++nt4) {
                    ldsm_x4_t(bfr[nt4], (uint32_t)__cvta_generic_to_shared(
                        &Wc[krow * WPITCH + wn * 32 + nt4 * 16 + noff]));
                }
#pragma unroll
                for (int nt = 0; nt < 4; ++nt)
                    mma16816(acc[nt], a,
                             bfr[nt >> 1][(nt & 1) * 2], bfr[nt >> 1][(nt & 1) * 2 + 1]);
            }
            if (c < 5) { storeX((c + 1) & 1); __syncthreads(); }
        }

        // ---- epilogue ----
        int row0 = bm + wm * 16 + (lane >> 2);
        int row1 = row0 + 8;
        float d0 = (row0 < NATOMS) ? (float)g_deg[row0] : 0.f;
        float d1 = (row1 < NATOMS) ? (float)g_deg[row1] : 0.f;
#pragma unroll
        for (int nt = 0; nt < 4; ++nt) {
            int col = colbase + nt * 8;
            if (row0 < NATOMS) {
                float2 o;
                o.x = acc[nt][0] + d0 * cv[nt].x + bv[nt].x;
                o.y = acc[nt][1] + d0 * cv[nt].y + bv[nt].y;
                *(float2*)&out[row0 * F + col] = o;
            }
            if (row1 < NATOMS) {
                float2 o;
                o.x = acc[nt][2] + d1 * cv[nt].x + bv[nt].x;
                o.y = acc[nt][3] + d1 * cv[nt].y + bv[nt].y;
                *(float2*)&out[row1 * F + col] = o;
            }
        }
        __syncthreads();                             // all deg reads + X reads done
        if (tid < 32) {
            int r = bm + tid;
            if (r < NATOMS) g_deg[r] = 0;            // invariant for next call
        }
    }
}

// ---------------------------------------------------------------------------
extern "C" void kernel_launch(void* const* d_in, const int* in_sizes, int n_in,
                              void* d_out, int out_size) {
    const float* feat  = (const float*)d_in[0];
    const void*  ei    = d_in[1];
    const float* W_msg = (const float*)d_in[2];
    const float* b_msg = (const float*)d_in[3];
    const float* W_upd = (const float*)d_in[4];
    const float* b_upd = (const float*)d_in[5];
    float*       out   = (float*)d_out;

    static int configured = 0;
    if (!configured) {
        cudaFuncSetAttribute(out_gemm, cudaFuncAttributeMaxDynamicSharedMemorySize,
                             GEMM_SMEM_BYTES);
        configured = 1;
    }

    prebuild_kernel<<<1250, 256>>>(feat, ei, W_msg, b_msg, W_upd);
    gather_kernel<<<(NATOMS * 32 + 255) / 256, 256>>>();
    out_gemm<<<GGRID, 256, GEMM_SMEM_BYTES>>>(b_upd, out);
}